// round 7
// baseline (speedup 1.0000x reference)
#include <cuda_runtime.h>
#include <cstdint>

// LIF recurrence: T=64 steps, B*N = 524288 independent lanes.
//   h = v + (x - v) * 0.5 ; s = (h>=1) ; v = s ? 0 : h
// Pure HBM stream: 134 MB in + 134 MB out.
// R7: 256-bit vector ld/st (sm_100+ ld.global.v8.f32 -> LDG.E.256).
// Same bytes in flight as R6 with HALF the L1tex queue entries per byte
// (cross-CTA L1tex-queue contention is the suspected 74% limiter).
// Structure otherwise identical to R1/R6: distance-1 scalar prefetch,
// unroll 4, plain loads/stores. 64-thread blocks keep 1024 CTAs (even
// per-SM balance like R6).

static constexpr int T = 64;

__device__ __forceinline__ void ldg256(const float* p, float4& lo, float4& hi)
{
    asm volatile("ld.global.v8.f32 {%0,%1,%2,%3,%4,%5,%6,%7}, [%8];"
                 : "=f"(lo.x), "=f"(lo.y), "=f"(lo.z), "=f"(lo.w),
                   "=f"(hi.x), "=f"(hi.y), "=f"(hi.z), "=f"(hi.w)
                 : "l"(p));
}

__device__ __forceinline__ void stg256(float* p, const float4 lo, const float4 hi)
{
    asm volatile("st.global.v8.f32 [%0], {%1,%2,%3,%4,%5,%6,%7,%8};"
                 :: "l"(p),
                    "f"(lo.x), "f"(lo.y), "f"(lo.z), "f"(lo.w),
                    "f"(hi.x), "f"(hi.y), "f"(hi.z), "f"(hi.w)
                 : "memory");
}

__device__ __forceinline__ void lif_step4(float4& v, const float4 xt, float4& s)
{
    float4 h;
    h.x = v.x + (xt.x - v.x) * 0.5f;
    h.y = v.y + (xt.y - v.y) * 0.5f;
    h.z = v.z + (xt.z - v.z) * 0.5f;
    h.w = v.w + (xt.w - v.w) * 0.5f;

    s.x = (h.x >= 1.0f) ? 1.0f : 0.0f;
    s.y = (h.y >= 1.0f) ? 1.0f : 0.0f;
    s.z = (h.z >= 1.0f) ? 1.0f : 0.0f;
    s.w = (h.w >= 1.0f) ? 1.0f : 0.0f;

    v.x = (h.x >= 1.0f) ? 0.0f : h.x;
    v.y = (h.y >= 1.0f) ? 0.0f : h.y;
    v.z = (h.z >= 1.0f) ? 0.0f : h.z;
    v.w = (h.w >= 1.0f) ? 0.0f : h.w;
}

__global__ void __launch_bounds__(64) lif_kernel(const float* __restrict__ x,
                                                 float* __restrict__ out,
                                                 int lanes8)  // B*N/8 per timestep
{
    int i = blockIdx.x * blockDim.x + threadIdx.x;
    if (i >= lanes8) return;

    size_t base = (size_t)i * 8;           // element offset within a plane
    size_t stride = (size_t)lanes8 * 8;    // elements per timestep plane

    float4 v0 = make_float4(0.f, 0.f, 0.f, 0.f);
    float4 v1 = make_float4(0.f, 0.f, 0.f, 0.f);

    // distance-1 scalar prefetch (R1/R6 structure)
    float4 a0, a1;
    ldg256(x + base, a0, a1);

    #pragma unroll 4
    for (int t = 0; t < T; ++t) {
        float4 n0, n1;
        if (t + 1 < T) ldg256(x + (size_t)(t + 1) * stride + base, n0, n1);

        float4 s0, s1;
        lif_step4(v0, a0, s0);
        lif_step4(v1, a1, s1);

        stg256(out + (size_t)t * stride + base, s0, s1);

        a0 = n0;
        a1 = n1;
    }
}

extern "C" void kernel_launch(void* const* d_in, const int* in_sizes, int n_in,
                              void* d_out, int out_size)
{
    const float* x = (const float*)d_in[0];
    float* out = (float*)d_out;

    int total = in_sizes[0];          // T * B * N
    int lanes = total / T;            // 524288
    int lanes8 = lanes / 8;           // 65536

    int threads = 64;                 // 1024 CTAs -> even per-SM balance
    int blocks = (lanes8 + threads - 1) / threads;
    lif_kernel<<<blocks, threads>>>(x, out, lanes8);
}